// round 15
// baseline (speedup 1.0000x reference)
#include <cuda_runtime.h>
#include <cuda_bf16.h>
#include <cstdint>
#include <cstddef>

// SRNN_multi: 2-layer spiking RNN, N=512, T=1000, H=128, DOUT=20.
//   prep:  permute weight matrices once into gmem
//   k1:    pre1 = x @ Wi1^T + bi1 + bh1    (R10 GEMM, 1 tile/CTA)
//   k2a:   s1(t) recurrence -> mask stream (dual-chain walk, 256 CTAs x 64)
//   k2b1:  gi(row,t) = b2 + s1(t)@Wi2^T    (10240-warp parallel, no smem)
//   k2b2:  s2(t) recurrence + counts       (R10: 1 row/warp, 256 CTAs x 64)
//   out = bo + (sum_t s2) @ Wo^T / T

#define NB   512
#define TS   1000
#define HD   128
#define DOUT 20
#define MTOT (NB * TS)
#define XS   66
#define NSTRIP 20               // k2b1 t-strips per row (50 t each)

typedef unsigned long long ull;

// pre1 scratch, permuted: [(row*TS+t)*128 + lane*4 + q] = val[lane + 32*q].
// Reused by k2b1 as gi storage. +2048 floats pad for deep prefetch overshoot.
__device__ float g_pre1[(size_t)MTOT * HD + 2048];
// s1 spike masks per (row,t): two 64-bit words (k 0-63, 64-127)
__device__ ulonglong2 g_s1[(size_t)NB * TS + 16];
// permuted weights: P[k*128 + (j&31)*4 + (j>>5)] = W[j*128 + k]
__device__ float g_Wi1p[HD * HD], g_Wh1p[HD * HD], g_Wi2p[HD * HD], g_Wh2p[HD * HD];

__device__ __forceinline__ ull pk2(float lo, float hi) {
    ull r; asm("mov.b64 %0, {%1, %2};" : "=l"(r) : "f"(lo), "f"(hi)); return r;
}
__device__ __forceinline__ float2 upk2(ull v) {
    float2 r; asm("mov.b64 {%0, %1}, %2;" : "=f"(r.x), "=f"(r.y) : "l"(v)); return r;
}
__device__ __forceinline__ void fma2(ull& d, ull a, ull b) {
    asm("fma.rn.f32x2 %0, %1, %2, %0;" : "+l"(d) : "l"(a), "l"(b));
}
__device__ __forceinline__ void add2(ull& d, ull a) {
    asm("add.rn.f32x2 %0, %1, %0;" : "+l"(d) : "l"(a));
}

// ---------------------------------------------------------------------------
// prep: one-time weight permutation.
// ---------------------------------------------------------------------------
__global__ void prep(const float* __restrict__ Wi1, const float* __restrict__ Wh1,
                     const float* __restrict__ Wi2, const float* __restrict__ Wh2)
{
    int i = blockIdx.x * blockDim.x + threadIdx.x;
    if (i < HD * HD) {
        int j = i >> 7, k = i & 127;
        int d = k * 128 + ((j & 31) << 2) + (j >> 5);
        g_Wi1p[d] = Wi1[i];
        g_Wh1p[d] = Wh1[i];
        g_Wi2p[d] = Wi2[i];
        g_Wh2p[d] = Wh2[i];
    }
}

// ---------------------------------------------------------------------------
// Kernel 1: pre1 = x @ Wi1^T + (bi1+bh1). R10 version, verbatim.
// 8000 CTAs x 256 thr; CTA = 64 rows; warp = 8 rows (4 row-pairs) x 128 cols.
// ---------------------------------------------------------------------------
__global__ void __launch_bounds__(256, 2) k1_gemm(
    const float* __restrict__ x, const float* __restrict__ bi1,
    const float* __restrict__ bh1)
{
    extern __shared__ float sm[];
    float* ws = sm;            // 16384 f: permuted Wi1
    float* xT = sm + 16384;    // 128*XS f: xT[k*XS + r]

    const int tid = threadIdx.x, lane = tid & 31, warp = tid >> 5;

    {
        const float4* Wp = (const float4*)g_Wi1p;
        float4* w4 = (float4*)ws;
        for (int i = tid; i < 4096; i += 256) w4[i] = Wp[i];
    }
    {
        const float4* xg = (const float4*)x + (size_t)blockIdx.x * 2048;
        for (int i = tid; i < 2048; i += 256) {
            float4 v = xg[i];
            int r = i >> 5, c = (i & 31) << 2;
            xT[(c + 0) * XS + r] = v.x;
            xT[(c + 1) * XS + r] = v.y;
            xT[(c + 2) * XS + r] = v.z;
            xT[(c + 3) * XS + r] = v.w;
        }
    }
    __syncthreads();

    ull acc[4][4];
#pragma unroll
    for (int q = 0; q < 4; ++q) {
        const float b = bi1[lane + 32 * q] + bh1[lane + 32 * q];
        const ull bd = pk2(b, b);
#pragma unroll
        for (int p = 0; p < 4; ++p) acc[q][p] = bd;
    }

    const float4* W4 = (const float4*)ws;
    const float* xw = xT + warp * 8;

#pragma unroll 4
    for (int k = 0; k < 128; ++k) {
        const float4 wv = W4[k * 32 + lane];
        const ull wd0 = pk2(wv.x, wv.x), wd1 = pk2(wv.y, wv.y);
        const ull wd2 = pk2(wv.z, wv.z), wd3 = pk2(wv.w, wv.w);
        const ull* xp = (const ull*)(xw + k * XS);
#pragma unroll
        for (int p = 0; p < 4; ++p) {
            const ull xv = xp[p];
            fma2(acc[0][p], xv, wd0);
            fma2(acc[1][p], xv, wd1);
            fma2(acc[2][p], xv, wd2);
            fma2(acc[3][p], xv, wd3);
        }
    }

    const size_t rbase = (size_t)blockIdx.x * 64 + warp * 8;
#pragma unroll
    for (int p = 0; p < 4; ++p) {
        const float2 a0 = upk2(acc[0][p]), a1 = upk2(acc[1][p]);
        const float2 a2 = upk2(acc[2][p]), a3 = upk2(acc[3][p]);
        float4 e; e.x = a0.x; e.y = a1.x; e.z = a2.x; e.w = a3.x;
        float4 o; o.x = a0.y; o.y = a1.y; o.z = a2.y; o.w = a3.y;
        *(float4*)(g_pre1 + (rbase + 2 * p)     * 128 + lane * 4) = e;
        *(float4*)(g_pre1 + (rbase + 2 * p + 1) * 128 + lane * 4) = o;
    }
}

// ---------------------------------------------------------------------------
// Single-chain branchless walk (ascending k) — used by k2b1/k2b2 (order
// unchanged there).
// ---------------------------------------------------------------------------
__device__ __forceinline__ int nextbit(ull& m0, ull& m1) {
    const bool lo = (m0 != 0ull);
    const ull  w  = lo ? m0 : m1;
    const ull  wc = w & (w - 1);
    const int  k  = (lo ? 0 : 64) + __ffsll((long long)w) - 1;
    m0 = lo ? wc : m0;
    m1 = lo ? m1 : wc;
    return k;
}

__device__ __forceinline__ void walkp(
    const ulonglong2* __restrict__ W, ull m0, ull m1, int lane, ull& a, ull& b)
{
    int n = __popcll(m0) + __popcll(m1);
    if (n == 0) return;
    ulonglong2 va = W[nextbit(m0, m1) * 32 + lane];
    if (n >= 2) {
        ulonglong2 vb = W[nextbit(m0, m1) * 32 + lane];
        for (int i = 2; i < n; ++i) {
            ulonglong2 vc = W[nextbit(m0, m1) * 32 + lane];
            add2(a, va.x); add2(b, va.y);
            va = vb; vb = vc;
        }
        add2(a, va.x); add2(b, va.y);
        va = vb;
    }
    add2(a, va.x); add2(b, va.y);
}

// ---------------------------------------------------------------------------
// Dual-chain walk: the two 64-bit mask words advance as independent pipelined
// chains (parallel ffs spines), interleaved adds. Used by k2a only.
// ---------------------------------------------------------------------------
__device__ __forceinline__ int nb64(ull& m, int base) {
    const int k = base + __ffsll((long long)m) - 1;
    m &= m - 1;
    return k;
}

__device__ __forceinline__ void walk2(
    const ulonglong2* __restrict__ W, ull m0, ull m1, int lane, ull& a, ull& b)
{
    int n0 = __popcll(m0), n1 = __popcll(m1);

    if (n0 && n1) {                       // warp-uniform branch (mask is uniform)
        const int c = (n0 < n1 ? n0 : n1);
        ulonglong2 v0 = W[nb64(m0, 0)  * 32 + lane];
        ulonglong2 v1 = W[nb64(m1, 64) * 32 + lane];
        for (int i = 1; i < c; ++i) {
            ulonglong2 w0 = W[nb64(m0, 0)  * 32 + lane];
            ulonglong2 w1 = W[nb64(m1, 64) * 32 + lane];
            add2(a, v0.x); add2(b, v0.y);
            add2(a, v1.x); add2(b, v1.y);
            v0 = w0; v1 = w1;
        }
        add2(a, v0.x); add2(b, v0.y);
        add2(a, v1.x); add2(b, v1.y);
        n0 -= c; n1 -= c;
    }
    // tail: at most one word still has bits
    const bool lo = (n0 != 0);
    int  n = lo ? n0 : n1;
    if (n) {
        ull  m = lo ? m0 : m1;
        const int base = lo ? 0 : 64;
        ulonglong2 v = W[nb64(m, base) * 32 + lane];
        for (int i = 1; i < n; ++i) {
            ulonglong2 w = W[nb64(m, base) * 32 + lane];
            add2(a, v.x); add2(b, v.y);
            v = w;
        }
        add2(a, v.x); add2(b, v.y);
    }
}

// predicated lane-0 store (no BSSY/BSYNC)
__device__ __forceinline__ void stg_mask(ulonglong2* p, ull lo, ull hi, int lane) {
    asm volatile(
        "{\n\t.reg .pred p0;\n\tsetp.eq.s32 p0, %0, 0;\n\t"
        "@p0 st.global.v2.u64 [%1], {%2, %3};\n\t}"
        :: "r"(lane), "l"(p), "l"(lo), "l"(hi) : "memory");
}

// ---------------------------------------------------------------------------
// Kernel 2a: layer-1 recurrence. 256 CTAs x 64 thr, 1 row/warp,
// dual-chain walk on the critical path.
// ---------------------------------------------------------------------------
__global__ void __launch_bounds__(64) k2a(void)
{
    extern __shared__ float sm[];      // 16384 f = permuted Wh1
    const int tid = threadIdx.x, lane = tid & 31, warp = tid >> 5;

    {
        const float4* Wp = (const float4*)g_Wh1p;
        float4* w4 = (float4*)sm;
        for (int i = tid; i < 4096; i += 64) w4[i] = Wp[i];
    }
    __syncthreads();

    const ulonglong2* W1 = (const ulonglong2*)sm;
    const int row = blockIdx.x * 2 + warp;
    const float4* pre = (const float4*)g_pre1 + (size_t)row * TS * 32 + lane;
    ulonglong2* ms = g_s1 + (size_t)row * TS;

    ull s_lo = 0, s_hi = 0;

    float4 f0 = pre[0 * 32], f1 = pre[1 * 32], f2 = pre[2 * 32], f3 = pre[3 * 32];
    float4 f4 = pre[4 * 32], f5 = pre[5 * 32], f6 = pre[6 * 32], f7 = pre[7 * 32];

    auto step = [&](const float4& cur, int t) {
        ull h01 = pk2(cur.x, cur.y), h23 = pk2(cur.z, cur.w);
        walk2(W1, s_lo, s_hi, lane, h01, h23);
        const float2 ha = upk2(h01), hb = upk2(h23);
        const unsigned q0 = __ballot_sync(0xffffffffu, ha.x >= 1.0f);
        const unsigned q1 = __ballot_sync(0xffffffffu, ha.y >= 1.0f);
        const unsigned q2 = __ballot_sync(0xffffffffu, hb.x >= 1.0f);
        const unsigned q3 = __ballot_sync(0xffffffffu, hb.y >= 1.0f);
        s_lo = (ull)q0 | ((ull)q1 << 32);
        s_hi = (ull)q2 | ((ull)q3 << 32);
        stg_mask(ms + t, s_lo, s_hi, lane);
    };

    for (int t = 0; t < TS; t += 8) {
        step(f0, t + 0); f0 = pre[(t +  8) * 32];
        step(f1, t + 1); f1 = pre[(t +  9) * 32];
        step(f2, t + 2); f2 = pre[(t + 10) * 32];
        step(f3, t + 3); f3 = pre[(t + 11) * 32];
        step(f4, t + 4); f4 = pre[(t + 12) * 32];
        step(f5, t + 5); f5 = pre[(t + 13) * 32];
        step(f6, t + 6); f6 = pre[(t + 14) * 32];
        step(f7, t + 7); f7 = pre[(t + 15) * 32];
    }
}

// ---------------------------------------------------------------------------
// Kernel 2b1: gi(row,t) = b2 + s1(t)@Wi2^T. 1280 CTAs x 256 thr = 10240
// warps; warp w: row = w/20, t-strip = (w%20)*50. Weights via L1-resident
// gmem. Same walkp / same order / same indexing as the measured R12 version —
// only the warp count changed (4096 -> 10240) to lift occupancy.
// ---------------------------------------------------------------------------
__global__ void __launch_bounds__(256) k2b1(
    const float* __restrict__ bi2, const float* __restrict__ bh2)
{
    const int tid = threadIdx.x, lane = tid & 31;
    const int w     = blockIdx.x * 8 + (tid >> 5);
    const int row   = w / NSTRIP;
    const int strip = w - row * NSTRIP;
    const int t0    = strip * (TS / NSTRIP);
    const int t1    = t0 + (TS / NSTRIP);

    const ulonglong2* W2i = (const ulonglong2*)(const void*)g_Wi2p;

    const ull b01 = pk2(bi2[lane]      + bh2[lane],      bi2[lane + 32] + bh2[lane + 32]);
    const ull b23 = pk2(bi2[lane + 64] + bh2[lane + 64], bi2[lane + 96] + bh2[lane + 96]);

    const ulonglong2* ms = g_s1 + (size_t)row * TS;
    ulonglong2* gi = (ulonglong2*)(void*)g_pre1 + (size_t)row * TS * 32 + lane;

    ulonglong2 mA = ms[t0], mB = ms[t0 + 1];
    for (int t = t0; t < t1; ++t) {
        const ulonglong2 m = mA;
        mA = mB;
        mB = ms[min(t + 2, t1 - 1)];
        ull g01 = b01, g23 = b23;
        walkp(W2i, m.x, m.y, lane, g01, g23);
        ulonglong2 o; o.x = g01; o.y = g23;
        gi[(size_t)t * 32] = o;
    }
}

// ---------------------------------------------------------------------------
// Kernel 2b2: layer-2 recurrence + counts + output.
// R10 version: 256 CTAs x 64 thr, 1 row/warp, gi prefetched 8 deep.
// ---------------------------------------------------------------------------
__global__ void __launch_bounds__(64) k2b2(
    const float* __restrict__ Wo, const float* __restrict__ bo,
    float* __restrict__ out)
{
    extern __shared__ float sm[];      // 16384 f = permuted Wh2
    const int tid = threadIdx.x, lane = tid & 31, warp = tid >> 5;

    {
        const float4* Wp = (const float4*)g_Wh2p;
        float4* w4 = (float4*)sm;
        for (int i = tid; i < 4096; i += 64) w4[i] = Wp[i];
    }
    __syncthreads();

    const ulonglong2* W2h = (const ulonglong2*)sm;
    const int row = blockIdx.x * 2 + warp;
    const float4* gi = (const float4*)g_pre1 + (size_t)row * TS * 32 + lane;

    ull r2_lo = 0, r2_hi = 0;
    int c0 = 0, c1 = 0, c2 = 0, c3 = 0;

    float4 f0 = gi[0 * 32], f1 = gi[1 * 32], f2 = gi[2 * 32], f3 = gi[3 * 32];
    float4 f4 = gi[4 * 32], f5 = gi[5 * 32], f6 = gi[6 * 32], f7 = gi[7 * 32];

    auto stepB = [&](const float4& cur) {
        ull g01 = pk2(cur.x, cur.y), g23 = pk2(cur.z, cur.w);
        walkp(W2h, r2_lo, r2_hi, lane, g01, g23);
        const float2 ga = upk2(g01), gb = upk2(g23);
        const bool p0 = (ga.x >= 1.0f), p1 = (ga.y >= 1.0f);
        const bool p2 = (gb.x >= 1.0f), p3 = (gb.y >= 1.0f);
        const unsigned q0 = __ballot_sync(0xffffffffu, p0);
        const unsigned q1 = __ballot_sync(0xffffffffu, p1);
        const unsigned q2 = __ballot_sync(0xffffffffu, p2);
        const unsigned q3 = __ballot_sync(0xffffffffu, p3);
        r2_lo = (ull)q0 | ((ull)q1 << 32);
        r2_hi = (ull)q2 | ((ull)q3 << 32);
        c0 += p0; c1 += p1; c2 += p2; c3 += p3;
    };

    for (int t = 0; t < TS; t += 8) {
        stepB(f0); f0 = gi[(t +  8) * 32];
        stepB(f1); f1 = gi[(t +  9) * 32];
        stepB(f2); f2 = gi[(t + 10) * 32];
        stepB(f3); f3 = gi[(t + 11) * 32];
        stepB(f4); f4 = gi[(t + 12) * 32];
        stepB(f5); f5 = gi[(t + 13) * 32];
        stepB(f6); f6 = gi[(t + 14) * 32];
        stepB(f7); f7 = gi[(t + 15) * 32];
    }

    // out[row] = bo + counts @ Wo^T / T
    const float f0c = (float)c0, f1c = (float)c1, f2c = (float)c2, f3c = (float)c3;
#pragma unroll
    for (int o = 0; o < DOUT; ++o) {
        const float* wr = Wo + o * HD;
        float p = f0c * wr[lane] + f1c * wr[lane + 32]
                + f2c * wr[lane + 64] + f3c * wr[lane + 96];
#pragma unroll
        for (int s = 16; s; s >>= 1) p += __shfl_xor_sync(0xffffffffu, p, s);
        if (lane == 0) out[row * DOUT + o] = bo[o] + p * (1.0f / (float)TS);
    }
}

extern "C" void kernel_launch(void* const* d_in, const int* in_sizes, int n_in,
                              void* d_out, int out_size)
{
    const float* x   = (const float*)d_in[0];
    const float* Wi1 = (const float*)d_in[1];
    const float* bi1 = (const float*)d_in[2];
    const float* Wh1 = (const float*)d_in[3];
    const float* bh1 = (const float*)d_in[4];
    const float* Wi2 = (const float*)d_in[5];
    const float* bi2 = (const float*)d_in[6];
    const float* Wh2 = (const float*)d_in[7];
    const float* bh2 = (const float*)d_in[8];
    const float* Wo  = (const float*)d_in[9];
    const float* bo  = (const float*)d_in[10];
    float* out = (float*)d_out;

    const int k1_smem = (16384 + 128 * XS) * 4;   // 99328 B, 2 CTAs/SM
    const int w_smem  = 16384 * 4;                // 65536 B
    cudaFuncSetAttribute(k1_gemm, cudaFuncAttributeMaxDynamicSharedMemorySize, k1_smem);
    cudaFuncSetAttribute(k2a,  cudaFuncAttributeMaxDynamicSharedMemorySize, w_smem);
    cudaFuncSetAttribute(k2b2, cudaFuncAttributeMaxDynamicSharedMemorySize, w_smem);

    prep<<<64, 256>>>(Wi1, Wh1, Wi2, Wh2);
    k1_gemm<<<MTOT / 64, 256, k1_smem>>>(x, bi1, bh1);
    k2a<<<NB / 2, 64, w_smem>>>();
    k2b1<<<NB * NSTRIP / 8, 256>>>(bi2, bh2);
    k2b2<<<NB / 2, 64, w_smem>>>(Wo, bo, out);
}

// round 16
// speedup vs baseline: 1.0637x; 1.0637x over previous
#include <cuda_runtime.h>
#include <cuda_bf16.h>
#include <cstdint>
#include <cstddef>

// SRNN_multi: 2-layer spiking RNN, N=512, T=1000, H=128, DOUT=20.
//   prep:  permute weight matrices once into gmem
//   k1:    pre1 = x @ Wi1^T + bi1 + bh1    (16 rows/warp, issue-lean GEMM)
//   k2a:   s1(t) recurrence -> mask stream (R14: walkp, 256 CTAs x 64)
//   k2b1:  gi(row,t) = b2 + s1(t)@Wi2^T    (10240-warp parallel, no smem)
//   k2b2:  s2(t) recurrence + counts       (R10: 1 row/warp, 256 CTAs x 64)
//   out = bo + (sum_t s2) @ Wo^T / T

#define NB   512
#define TS   1000
#define HD   128
#define DOUT 20
#define MTOT (NB * TS)
#define XS   68                 // xT k-stride in floats (16B-aligned rows)
#define NSTRIP 20               // k2b1 t-strips per row (50 t each)

typedef unsigned long long ull;

// pre1 scratch, permuted: [(row*TS+t)*128 + lane*4 + q] = val[lane + 32*q].
// Reused by k2b1 as gi storage. +2048 floats pad for deep prefetch overshoot.
__device__ float g_pre1[(size_t)MTOT * HD + 2048];
// s1 spike masks per (row,t): two 64-bit words (k 0-63, 64-127)
__device__ ulonglong2 g_s1[(size_t)NB * TS + 16];
// permuted weights: P[k*128 + (j&31)*4 + (j>>5)] = W[j*128 + k]
__device__ float g_Wi1p[HD * HD], g_Wh1p[HD * HD], g_Wi2p[HD * HD], g_Wh2p[HD * HD];

__device__ __forceinline__ ull pk2(float lo, float hi) {
    ull r; asm("mov.b64 %0, {%1, %2};" : "=l"(r) : "f"(lo), "f"(hi)); return r;
}
__device__ __forceinline__ float2 upk2(ull v) {
    float2 r; asm("mov.b64 {%0, %1}, %2;" : "=f"(r.x), "=f"(r.y) : "l"(v)); return r;
}
__device__ __forceinline__ void fma2(ull& d, ull a, ull b) {
    asm("fma.rn.f32x2 %0, %1, %2, %0;" : "+l"(d) : "l"(a), "l"(b));
}
__device__ __forceinline__ void add2(ull& d, ull a) {
    asm("add.rn.f32x2 %0, %1, %0;" : "+l"(d) : "l"(a));
}

// ---------------------------------------------------------------------------
// prep: one-time weight permutation.
// ---------------------------------------------------------------------------
__global__ void prep(const float* __restrict__ Wi1, const float* __restrict__ Wh1,
                     const float* __restrict__ Wi2, const float* __restrict__ Wh2)
{
    int i = blockIdx.x * blockDim.x + threadIdx.x;
    if (i < HD * HD) {
        int j = i >> 7, k = i & 127;
        int d = k * 128 + ((j & 31) << 2) + (j >> 5);
        g_Wi1p[d] = Wi1[i];
        g_Wh1p[d] = Wh1[i];
        g_Wi2p[d] = Wi2[i];
        g_Wh2p[d] = Wh2[i];
    }
}

// ---------------------------------------------------------------------------
// Kernel 1: pre1 = x @ Wi1^T + (bi1+bh1).
// 8000 CTAs x 128 thr; CTA = 64 rows; warp = 16 rows (8 row-pairs) x 128 cols.
// Per k: 1 LDS.128 (w) + 4 pk2 + 4 LDS.128 (x row-pairs) + 32 FFMA2 —
// 1.3 issue slots per fma op (was 1.7 at 8 rows/warp) -> fma-bound.
// Accumulation order per element unchanged: bias, then k ascending.
// ---------------------------------------------------------------------------
__global__ void __launch_bounds__(128, 2) k1_gemm(
    const float* __restrict__ x, const float* __restrict__ bi1,
    const float* __restrict__ bh1)
{
    extern __shared__ float sm[];
    float* ws = sm;            // 16384 f: permuted Wi1
    float* xT = sm + 16384;    // 128*XS f: xT[k*XS + r], r in [0,64)

    const int tid = threadIdx.x, lane = tid & 31, warp = tid >> 5;

    {
        const float4* Wp = (const float4*)g_Wi1p;
        float4* w4 = (float4*)ws;
        for (int i = tid; i < 4096; i += 128) w4[i] = Wp[i];
    }
    {
        const float4* xg = (const float4*)x + (size_t)blockIdx.x * 2048;
        for (int i = tid; i < 2048; i += 128) {
            float4 v = xg[i];
            int r = i >> 5, c = (i & 31) << 2;
            xT[(c + 0) * XS + r] = v.x;
            xT[(c + 1) * XS + r] = v.y;
            xT[(c + 2) * XS + r] = v.z;
            xT[(c + 3) * XS + r] = v.w;
        }
    }
    __syncthreads();

    ull acc[4][8];
#pragma unroll
    for (int q = 0; q < 4; ++q) {
        const float b = bi1[lane + 32 * q] + bh1[lane + 32 * q];
        const ull bd = pk2(b, b);
#pragma unroll
        for (int p = 0; p < 8; ++p) acc[q][p] = bd;
    }

    const float4* W4 = (const float4*)ws;
    const float* xw = xT + warp * 16;      // 16 rows for this warp; 64B aligned

#pragma unroll 4
    for (int k = 0; k < 128; ++k) {
        const float4 wv = W4[k * 32 + lane];
        const ull wd0 = pk2(wv.x, wv.x), wd1 = pk2(wv.y, wv.y);
        const ull wd2 = pk2(wv.z, wv.z), wd3 = pk2(wv.w, wv.w);
        const ulonglong2* xp2 = (const ulonglong2*)(xw + k * XS);  // 16B aligned
#pragma unroll
        for (int pp = 0; pp < 4; ++pp) {
            const ulonglong2 xv = xp2[pp];     // two row-pairs, warp-uniform
            fma2(acc[0][2 * pp],     xv.x, wd0);
            fma2(acc[1][2 * pp],     xv.x, wd1);
            fma2(acc[2][2 * pp],     xv.x, wd2);
            fma2(acc[3][2 * pp],     xv.x, wd3);
            fma2(acc[0][2 * pp + 1], xv.y, wd0);
            fma2(acc[1][2 * pp + 1], xv.y, wd1);
            fma2(acc[2][2 * pp + 1], xv.y, wd2);
            fma2(acc[3][2 * pp + 1], xv.y, wd3);
        }
    }

    const size_t rbase = (size_t)blockIdx.x * 64 + warp * 16;
#pragma unroll
    for (int p = 0; p < 8; ++p) {
        const float2 a0 = upk2(acc[0][p]), a1 = upk2(acc[1][p]);
        const float2 a2 = upk2(acc[2][p]), a3 = upk2(acc[3][p]);
        float4 e; e.x = a0.x; e.y = a1.x; e.z = a2.x; e.w = a3.x;
        float4 o; o.x = a0.y; o.y = a1.y; o.z = a2.y; o.w = a3.y;
        *(float4*)(g_pre1 + (rbase + 2 * p)     * 128 + lane * 4) = e;
        *(float4*)(g_pre1 + (rbase + 2 * p + 1) * 128 + lane * 4) = o;
    }
}

// ---------------------------------------------------------------------------
// Single-chain branchless walk (ascending k) — the proven version.
// ---------------------------------------------------------------------------
__device__ __forceinline__ int nextbit(ull& m0, ull& m1) {
    const bool lo = (m0 != 0ull);
    const ull  w  = lo ? m0 : m1;
    const ull  wc = w & (w - 1);
    const int  k  = (lo ? 0 : 64) + __ffsll((long long)w) - 1;
    m0 = lo ? wc : m0;
    m1 = lo ? m1 : wc;
    return k;
}

__device__ __forceinline__ void walkp(
    const ulonglong2* __restrict__ W, ull m0, ull m1, int lane, ull& a, ull& b)
{
    int n = __popcll(m0) + __popcll(m1);
    if (n == 0) return;
    ulonglong2 va = W[nextbit(m0, m1) * 32 + lane];
    if (n >= 2) {
        ulonglong2 vb = W[nextbit(m0, m1) * 32 + lane];
        for (int i = 2; i < n; ++i) {
            ulonglong2 vc = W[nextbit(m0, m1) * 32 + lane];
            add2(a, va.x); add2(b, va.y);
            va = vb; vb = vc;
        }
        add2(a, va.x); add2(b, va.y);
        va = vb;
    }
    add2(a, va.x); add2(b, va.y);
}

// predicated lane-0 store (no BSSY/BSYNC)
__device__ __forceinline__ void stg_mask(ulonglong2* p, ull lo, ull hi, int lane) {
    asm volatile(
        "{\n\t.reg .pred p0;\n\tsetp.eq.s32 p0, %0, 0;\n\t"
        "@p0 st.global.v2.u64 [%1], {%2, %3};\n\t}"
        :: "r"(lane), "l"(p), "l"(lo), "l"(hi) : "memory");
}

// ---------------------------------------------------------------------------
// Kernel 2a: layer-1 recurrence. R14 version: 256 CTAs x 64 thr, 1 row/warp,
// single-chain walkp (dual-chain walk2 regressed in R15 — reverted).
// ---------------------------------------------------------------------------
__global__ void __launch_bounds__(64) k2a(void)
{
    extern __shared__ float sm[];      // 16384 f = permuted Wh1
    const int tid = threadIdx.x, lane = tid & 31, warp = tid >> 5;

    {
        const float4* Wp = (const float4*)g_Wh1p;
        float4* w4 = (float4*)sm;
        for (int i = tid; i < 4096; i += 64) w4[i] = Wp[i];
    }
    __syncthreads();

    const ulonglong2* W1 = (const ulonglong2*)sm;
    const int row = blockIdx.x * 2 + warp;
    const float4* pre = (const float4*)g_pre1 + (size_t)row * TS * 32 + lane;
    ulonglong2* ms = g_s1 + (size_t)row * TS;

    ull s_lo = 0, s_hi = 0;

    float4 f0 = pre[0 * 32], f1 = pre[1 * 32], f2 = pre[2 * 32], f3 = pre[3 * 32];
    float4 f4 = pre[4 * 32], f5 = pre[5 * 32], f6 = pre[6 * 32], f7 = pre[7 * 32];

    auto step = [&](const float4& cur, int t) {
        ull h01 = pk2(cur.x, cur.y), h23 = pk2(cur.z, cur.w);
        walkp(W1, s_lo, s_hi, lane, h01, h23);
        const float2 ha = upk2(h01), hb = upk2(h23);
        const unsigned q0 = __ballot_sync(0xffffffffu, ha.x >= 1.0f);
        const unsigned q1 = __ballot_sync(0xffffffffu, ha.y >= 1.0f);
        const unsigned q2 = __ballot_sync(0xffffffffu, hb.x >= 1.0f);
        const unsigned q3 = __ballot_sync(0xffffffffu, hb.y >= 1.0f);
        s_lo = (ull)q0 | ((ull)q1 << 32);
        s_hi = (ull)q2 | ((ull)q3 << 32);
        stg_mask(ms + t, s_lo, s_hi, lane);
    };

    for (int t = 0; t < TS; t += 8) {
        step(f0, t + 0); f0 = pre[(t +  8) * 32];
        step(f1, t + 1); f1 = pre[(t +  9) * 32];
        step(f2, t + 2); f2 = pre[(t + 10) * 32];
        step(f3, t + 3); f3 = pre[(t + 11) * 32];
        step(f4, t + 4); f4 = pre[(t + 12) * 32];
        step(f5, t + 5); f5 = pre[(t + 13) * 32];
        step(f6, t + 6); f6 = pre[(t + 14) * 32];
        step(f7, t + 7); f7 = pre[(t + 15) * 32];
    }
}

// ---------------------------------------------------------------------------
// Kernel 2b1: gi(row,t) = b2 + s1(t)@Wi2^T. Measured-good R15 config:
// 1280 CTAs x 256 thr = 10240 warps; warp w: row = w/20, t-strip 50.
// Weights via L1-resident gmem.
// ---------------------------------------------------------------------------
__global__ void __launch_bounds__(256) k2b1(
    const float* __restrict__ bi2, const float* __restrict__ bh2)
{
    const int tid = threadIdx.x, lane = tid & 31;
    const int w     = blockIdx.x * 8 + (tid >> 5);
    const int row   = w / NSTRIP;
    const int strip = w - row * NSTRIP;
    const int t0    = strip * (TS / NSTRIP);
    const int t1    = t0 + (TS / NSTRIP);

    const ulonglong2* W2i = (const ulonglong2*)(const void*)g_Wi2p;

    const ull b01 = pk2(bi2[lane]      + bh2[lane],      bi2[lane + 32] + bh2[lane + 32]);
    const ull b23 = pk2(bi2[lane + 64] + bh2[lane + 64], bi2[lane + 96] + bh2[lane + 96]);

    const ulonglong2* ms = g_s1 + (size_t)row * TS;
    ulonglong2* gi = (ulonglong2*)(void*)g_pre1 + (size_t)row * TS * 32 + lane;

    ulonglong2 mA = ms[t0], mB = ms[t0 + 1];
    for (int t = t0; t < t1; ++t) {
        const ulonglong2 m = mA;
        mA = mB;
        mB = ms[min(t + 2, t1 - 1)];
        ull g01 = b01, g23 = b23;
        walkp(W2i, m.x, m.y, lane, g01, g23);
        ulonglong2 o; o.x = g01; o.y = g23;
        gi[(size_t)t * 32] = o;
    }
}

// ---------------------------------------------------------------------------
// Kernel 2b2: layer-2 recurrence + counts + output.
// R10 version: 256 CTAs x 64 thr, 1 row/warp, gi prefetched 8 deep.
// ---------------------------------------------------------------------------
__global__ void __launch_bounds__(64) k2b2(
    const float* __restrict__ Wo, const float* __restrict__ bo,
    float* __restrict__ out)
{
    extern __shared__ float sm[];      // 16384 f = permuted Wh2
    const int tid = threadIdx.x, lane = tid & 31, warp = tid >> 5;

    {
        const float4* Wp = (const float4*)g_Wh2p;
        float4* w4 = (float4*)sm;
        for (int i = tid; i < 4096; i += 64) w4[i] = Wp[i];
    }
    __syncthreads();

    const ulonglong2* W2h = (const ulonglong2*)sm;
    const int row = blockIdx.x * 2 + warp;
    const float4* gi = (const float4*)g_pre1 + (size_t)row * TS * 32 + lane;

    ull r2_lo = 0, r2_hi = 0;
    int c0 = 0, c1 = 0, c2 = 0, c3 = 0;

    float4 f0 = gi[0 * 32], f1 = gi[1 * 32], f2 = gi[2 * 32], f3 = gi[3 * 32];
    float4 f4 = gi[4 * 32], f5 = gi[5 * 32], f6 = gi[6 * 32], f7 = gi[7 * 32];

    auto stepB = [&](const float4& cur) {
        ull g01 = pk2(cur.x, cur.y), g23 = pk2(cur.z, cur.w);
        walkp(W2h, r2_lo, r2_hi, lane, g01, g23);
        const float2 ga = upk2(g01), gb = upk2(g23);
        const bool p0 = (ga.x >= 1.0f), p1 = (ga.y >= 1.0f);
        const bool p2 = (gb.x >= 1.0f), p3 = (gb.y >= 1.0f);
        const unsigned q0 = __ballot_sync(0xffffffffu, p0);
        const unsigned q1 = __ballot_sync(0xffffffffu, p1);
        const unsigned q2 = __ballot_sync(0xffffffffu, p2);
        const unsigned q3 = __ballot_sync(0xffffffffu, p3);
        r2_lo = (ull)q0 | ((ull)q1 << 32);
        r2_hi = (ull)q2 | ((ull)q3 << 32);
        c0 += p0; c1 += p1; c2 += p2; c3 += p3;
    };

    for (int t = 0; t < TS; t += 8) {
        stepB(f0); f0 = gi[(t +  8) * 32];
        stepB(f1); f1 = gi[(t +  9) * 32];
        stepB(f2); f2 = gi[(t + 10) * 32];
        stepB(f3); f3 = gi[(t + 11) * 32];
        stepB(f4); f4 = gi[(t + 12) * 32];
        stepB(f5); f5 = gi[(t + 13) * 32];
        stepB(f6); f6 = gi[(t + 14) * 32];
        stepB(f7); f7 = gi[(t + 15) * 32];
    }

    // out[row] = bo + counts @ Wo^T / T
    const float f0c = (float)c0, f1c = (float)c1, f2c = (float)c2, f3c = (float)c3;
#pragma unroll
    for (int o = 0; o < DOUT; ++o) {
        const float* wr = Wo + o * HD;
        float p = f0c * wr[lane] + f1c * wr[lane + 32]
                + f2c * wr[lane + 64] + f3c * wr[lane + 96];
#pragma unroll
        for (int s = 16; s; s >>= 1) p += __shfl_xor_sync(0xffffffffu, p, s);
        if (lane == 0) out[row * DOUT + o] = bo[o] + p * (1.0f / (float)TS);
    }
}

extern "C" void kernel_launch(void* const* d_in, const int* in_sizes, int n_in,
                              void* d_out, int out_size)
{
    const float* x   = (const float*)d_in[0];
    const float* Wi1 = (const float*)d_in[1];
    const float* bi1 = (const float*)d_in[2];
    const float* Wh1 = (const float*)d_in[3];
    const float* bh1 = (const float*)d_in[4];
    const float* Wi2 = (const float*)d_in[5];
    const float* bi2 = (const float*)d_in[6];
    const float* Wh2 = (const float*)d_in[7];
    const float* bh2 = (const float*)d_in[8];
    const float* Wo  = (const float*)d_in[9];
    const float* bo  = (const float*)d_in[10];
    float* out = (float*)d_out;

    const int k1_smem = (16384 + 128 * XS) * 4;   // 100352 B, 2 CTAs/SM
    const int w_smem  = 16384 * 4;                // 65536 B
    cudaFuncSetAttribute(k1_gemm, cudaFuncAttributeMaxDynamicSharedMemorySize, k1_smem);
    cudaFuncSetAttribute(k2a,  cudaFuncAttributeMaxDynamicSharedMemorySize, w_smem);
    cudaFuncSetAttribute(k2b2, cudaFuncAttributeMaxDynamicSharedMemorySize, w_smem);

    prep<<<64, 256>>>(Wi1, Wh1, Wi2, Wh2);
    k1_gemm<<<MTOT / 64, 128, k1_smem>>>(x, bi1, bh1);
    k2a<<<NB / 2, 64, w_smem>>>();
    k2b1<<<NB * NSTRIP / 8, 256>>>(bi2, bh2);
    k2b2<<<NB / 2, 64, w_smem>>>(Wo, bo, out);
}

// round 17
// speedup vs baseline: 1.2466x; 1.1720x over previous
#include <cuda_runtime.h>
#include <cuda_bf16.h>
#include <cstdint>
#include <cstddef>

// SRNN_multi: 2-layer spiking RNN, N=512, T=1000, H=128, DOUT=20.
// CHUNKED PIPELINE (5 chunks of 200 timesteps, 4 streams, fork-join events):
//   k1(c):   pre1 for t-chunk c (t-major tiles)      [stream 0, fma-bound]
//   k2a(c):  s1 recurrence chunk -> masks            [sA, latency-bound]
//   k2b1(c): gi = b2 + s1@Wi2^T for chunk            [sB, parallel]
//   k2b2(c): s2 recurrence + counts; epilogue at end [sC, latency-bound]
// All per-row arithmetic orders identical to the serial version.

#define NB   512
#define TS   1000
#define HD   128
#define DOUT 20
#define MTOT (NB * TS)
#define XS   66
#define NCH  5
#define TCH  200                 // timesteps per chunk (divisible by 8)

typedef unsigned long long ull;

// pre1 scratch, permuted: [(n*TS+t)*128 + lane*4 + q] = val[lane + 32*q].
// Reused by k2b1 as gi storage. +2048 floats pad for prefetch overshoot.
__device__ float g_pre1[(size_t)MTOT * HD + 2048];
// s1 spike masks per (row,t): two 64-bit words (k 0-63, 64-127)
__device__ ulonglong2 g_s1[(size_t)NB * TS + 16];
// permuted weights: P[k*128 + (j&31)*4 + (j>>5)] = W[j*128 + k]
__device__ float g_Wi1p[HD * HD], g_Wh1p[HD * HD], g_Wi2p[HD * HD], g_Wh2p[HD * HD];
// k2b2 cross-chunk state
__device__ ulonglong2 g_s2st[NB];
__device__ int4 g_cnt[NB * 32];

__device__ __forceinline__ ull pk2(float lo, float hi) {
    ull r; asm("mov.b64 %0, {%1, %2};" : "=l"(r) : "f"(lo), "f"(hi)); return r;
}
__device__ __forceinline__ float2 upk2(ull v) {
    float2 r; asm("mov.b64 {%0, %1}, %2;" : "=f"(r.x), "=f"(r.y) : "l"(v)); return r;
}
__device__ __forceinline__ void fma2(ull& d, ull a, ull b) {
    asm("fma.rn.f32x2 %0, %1, %2, %0;" : "+l"(d) : "l"(a), "l"(b));
}
__device__ __forceinline__ void add2(ull& d, ull a) {
    asm("add.rn.f32x2 %0, %1, %0;" : "+l"(d) : "l"(a));
}

// ---------------------------------------------------------------------------
// prep: one-time weight permutation.
// ---------------------------------------------------------------------------
__global__ void prep(const float* __restrict__ Wi1, const float* __restrict__ Wh1,
                     const float* __restrict__ Wi2, const float* __restrict__ Wh2)
{
    int i = blockIdx.x * blockDim.x + threadIdx.x;
    if (i < HD * HD) {
        int j = i >> 7, k = i & 127;
        int d = k * 128 + ((j & 31) << 2) + (j >> 5);
        g_Wi1p[d] = Wi1[i];
        g_Wh1p[d] = Wh1[i];
        g_Wi2p[d] = Wi2[i];
        g_Wh2p[d] = Wh2[i];
    }
}

// ---------------------------------------------------------------------------
// Kernel 1: pre1 = x @ Wi1^T + (bi1+bh1), for one t-chunk.
// t-MAJOR tiles: tile b -> t = t0 + b/8, n in [(b&7)*64, +64). 1600 CTAs/chunk.
// Inner loop = the proven R10 version verbatim (warp = 8 rows, acc[4][4]).
// ---------------------------------------------------------------------------
__global__ void __launch_bounds__(256, 2) k1_gemm(
    const float* __restrict__ x, const float* __restrict__ bi1,
    const float* __restrict__ bh1, int t0)
{
    extern __shared__ float sm[];
    float* ws = sm;            // 16384 f: permuted Wi1
    float* xT = sm + 16384;    // 128*XS f: xT[k*XS + r], r = n offset in tile

    const int tid = threadIdx.x, lane = tid & 31, warp = tid >> 5;
    const int t  = t0 + (blockIdx.x >> 3);
    const int n0 = (blockIdx.x & 7) << 6;

    {
        const float4* Wp = (const float4*)g_Wi1p;
        float4* w4 = (float4*)ws;
        for (int i = tid; i < 4096; i += 256) w4[i] = Wp[i];
    }
    {
        const float4* x4 = (const float4*)x;
        for (int i = tid; i < 2048; i += 256) {
            const int r = i >> 5, c4 = i & 31;
            const float4 v = x4[((size_t)(n0 + r) * TS + t) * 32 + c4];
            const int c = c4 << 2;
            xT[(c + 0) * XS + r] = v.x;
            xT[(c + 1) * XS + r] = v.y;
            xT[(c + 2) * XS + r] = v.z;
            xT[(c + 3) * XS + r] = v.w;
        }
    }
    __syncthreads();

    ull acc[4][4];
#pragma unroll
    for (int q = 0; q < 4; ++q) {
        const float b = bi1[lane + 32 * q] + bh1[lane + 32 * q];
        const ull bd = pk2(b, b);
#pragma unroll
        for (int p = 0; p < 4; ++p) acc[q][p] = bd;
    }

    const float4* W4 = (const float4*)ws;
    const float* xw = xT + warp * 8;

#pragma unroll 4
    for (int k = 0; k < 128; ++k) {
        const float4 wv = W4[k * 32 + lane];
        const ull wd0 = pk2(wv.x, wv.x), wd1 = pk2(wv.y, wv.y);
        const ull wd2 = pk2(wv.z, wv.z), wd3 = pk2(wv.w, wv.w);
        const ull* xp = (const ull*)(xw + k * XS);
#pragma unroll
        for (int p = 0; p < 4; ++p) {
            const ull xv = xp[p];
            fma2(acc[0][p], xv, wd0);
            fma2(acc[1][p], xv, wd1);
            fma2(acc[2][p], xv, wd2);
            fma2(acc[3][p], xv, wd3);
        }
    }

    const int nbase = n0 + warp * 8;
#pragma unroll
    for (int p = 0; p < 4; ++p) {
        const float2 a0 = upk2(acc[0][p]), a1 = upk2(acc[1][p]);
        const float2 a2 = upk2(acc[2][p]), a3 = upk2(acc[3][p]);
        float4 e; e.x = a0.x; e.y = a1.x; e.z = a2.x; e.w = a3.x;
        float4 o; o.x = a0.y; o.y = a1.y; o.z = a2.y; o.w = a3.y;
        const size_t r0 = (size_t)(nbase + 2 * p) * TS + t;
        const size_t r1 = (size_t)(nbase + 2 * p + 1) * TS + t;
        *(float4*)(g_pre1 + r0 * 128 + lane * 4) = e;
        *(float4*)(g_pre1 + r1 * 128 + lane * 4) = o;
    }
}

// ---------------------------------------------------------------------------
// Single-chain branchless walk (ascending k) — the proven version.
// ---------------------------------------------------------------------------
__device__ __forceinline__ int nextbit(ull& m0, ull& m1) {
    const bool lo = (m0 != 0ull);
    const ull  w  = lo ? m0 : m1;
    const ull  wc = w & (w - 1);
    const int  k  = (lo ? 0 : 64) + __ffsll((long long)w) - 1;
    m0 = lo ? wc : m0;
    m1 = lo ? m1 : wc;
    return k;
}

__device__ __forceinline__ void walkp(
    const ulonglong2* __restrict__ W, ull m0, ull m1, int lane, ull& a, ull& b)
{
    int n = __popcll(m0) + __popcll(m1);
    if (n == 0) return;
    ulonglong2 va = W[nextbit(m0, m1) * 32 + lane];
    if (n >= 2) {
        ulonglong2 vb = W[nextbit(m0, m1) * 32 + lane];
        for (int i = 2; i < n; ++i) {
            ulonglong2 vc = W[nextbit(m0, m1) * 32 + lane];
            add2(a, va.x); add2(b, va.y);
            va = vb; vb = vc;
        }
        add2(a, va.x); add2(b, va.y);
        va = vb;
    }
    add2(a, va.x); add2(b, va.y);
}

// predicated lane-0 store (no BSSY/BSYNC)
__device__ __forceinline__ void stg_mask(ulonglong2* p, ull lo, ull hi, int lane) {
    asm volatile(
        "{\n\t.reg .pred p0;\n\tsetp.eq.s32 p0, %0, 0;\n\t"
        "@p0 st.global.v2.u64 [%1], {%2, %3};\n\t}"
        :: "r"(lane), "l"(p), "l"(lo), "l"(hi) : "memory");
}

// ---------------------------------------------------------------------------
// Kernel 2a: layer-1 recurrence for one t-chunk. 256 CTAs x 64, 1 row/warp.
// Cross-chunk state = the mask at t0-1 (already in g_s1 -> exact).
// ---------------------------------------------------------------------------
__global__ void __launch_bounds__(64) k2a(int t0)
{
    extern __shared__ float sm[];      // 16384 f = permuted Wh1
    const int tid = threadIdx.x, lane = tid & 31, warp = tid >> 5;

    {
        const float4* Wp = (const float4*)g_Wh1p;
        float4* w4 = (float4*)sm;
        for (int i = tid; i < 4096; i += 64) w4[i] = Wp[i];
    }
    __syncthreads();

    const ulonglong2* W1 = (const ulonglong2*)sm;
    const int row = blockIdx.x * 2 + warp;
    const float4* pre = (const float4*)g_pre1 + (size_t)row * TS * 32 + lane;
    ulonglong2* ms = g_s1 + (size_t)row * TS;

    ull s_lo = 0, s_hi = 0;
    if (t0 > 0) { const ulonglong2 m = ms[t0 - 1]; s_lo = m.x; s_hi = m.y; }

    float4 f0 = pre[(t0 + 0) * 32], f1 = pre[(t0 + 1) * 32];
    float4 f2 = pre[(t0 + 2) * 32], f3 = pre[(t0 + 3) * 32];
    float4 f4 = pre[(t0 + 4) * 32], f5 = pre[(t0 + 5) * 32];
    float4 f6 = pre[(t0 + 6) * 32], f7 = pre[(t0 + 7) * 32];

    auto step = [&](const float4& cur, int t) {
        ull h01 = pk2(cur.x, cur.y), h23 = pk2(cur.z, cur.w);
        walkp(W1, s_lo, s_hi, lane, h01, h23);
        const float2 ha = upk2(h01), hb = upk2(h23);
        const unsigned q0 = __ballot_sync(0xffffffffu, ha.x >= 1.0f);
        const unsigned q1 = __ballot_sync(0xffffffffu, ha.y >= 1.0f);
        const unsigned q2 = __ballot_sync(0xffffffffu, hb.x >= 1.0f);
        const unsigned q3 = __ballot_sync(0xffffffffu, hb.y >= 1.0f);
        s_lo = (ull)q0 | ((ull)q1 << 32);
        s_hi = (ull)q2 | ((ull)q3 << 32);
        stg_mask(ms + t, s_lo, s_hi, lane);
    };

    for (int t = t0; t < t0 + TCH; t += 8) {
        step(f0, t + 0); f0 = pre[(t +  8) * 32];
        step(f1, t + 1); f1 = pre[(t +  9) * 32];
        step(f2, t + 2); f2 = pre[(t + 10) * 32];
        step(f3, t + 3); f3 = pre[(t + 11) * 32];
        step(f4, t + 4); f4 = pre[(t + 12) * 32];
        step(f5, t + 5); f5 = pre[(t + 13) * 32];
        step(f6, t + 6); f6 = pre[(t + 14) * 32];
        step(f7, t + 7); f7 = pre[(t + 15) * 32];
    }
}

// ---------------------------------------------------------------------------
// Kernel 2b1: gi = b2 + s1@Wi2^T for one chunk. 256 CTAs x 256 = 2048 warps;
// warp w: row = w>>2, strip = (w&3)*50 within the chunk (same 50-t strips as
// the monolithic version -> identical order). L1-resident gmem weights.
// ---------------------------------------------------------------------------
__global__ void __launch_bounds__(256) k2b1(
    const float* __restrict__ bi2, const float* __restrict__ bh2, int t0)
{
    const int tid = threadIdx.x, lane = tid & 31;
    const int w    = blockIdx.x * 8 + (tid >> 5);
    const int row  = w >> 2;
    const int ts   = t0 + (w & 3) * 50;
    const int te   = ts + 50;

    const ulonglong2* W2i = (const ulonglong2*)(const void*)g_Wi2p;

    const ull b01 = pk2(bi2[lane]      + bh2[lane],      bi2[lane + 32] + bh2[lane + 32]);
    const ull b23 = pk2(bi2[lane + 64] + bh2[lane + 64], bi2[lane + 96] + bh2[lane + 96]);

    const ulonglong2* ms = g_s1 + (size_t)row * TS;
    ulonglong2* gi = (ulonglong2*)(void*)g_pre1 + (size_t)row * TS * 32 + lane;

    ulonglong2 mA = ms[ts], mB = ms[ts + 1];
    for (int t = ts; t < te; ++t) {
        const ulonglong2 m = mA;
        mA = mB;
        mB = ms[min(t + 2, te - 1)];
        ull g01 = b01, g23 = b23;
        walkp(W2i, m.x, m.y, lane, g01, g23);
        ulonglong2 o; o.x = g01; o.y = g23;
        gi[(size_t)t * 32] = o;
    }
}

// ---------------------------------------------------------------------------
// Kernel 2b2: layer-2 recurrence + counts for one chunk; epilogue on last.
// 256 CTAs x 64, 1 row/warp. State: s2 mask (warp-uniform) + per-lane counts.
// ---------------------------------------------------------------------------
__global__ void __launch_bounds__(64) k2b2(
    const float* __restrict__ Wo, const float* __restrict__ bo,
    float* __restrict__ out, int t0)
{
    extern __shared__ float sm[];      // 16384 f = permuted Wh2
    const int tid = threadIdx.x, lane = tid & 31, warp = tid >> 5;

    {
        const float4* Wp = (const float4*)g_Wh2p;
        float4* w4 = (float4*)sm;
        for (int i = tid; i < 4096; i += 64) w4[i] = Wp[i];
    }
    __syncthreads();

    const ulonglong2* W2h = (const ulonglong2*)sm;
    const int row = blockIdx.x * 2 + warp;
    const float4* gi = (const float4*)g_pre1 + (size_t)row * TS * 32 + lane;

    ull r2_lo = 0, r2_hi = 0;
    int c0 = 0, c1 = 0, c2 = 0, c3 = 0;
    if (t0 > 0) {
        const ulonglong2 st = g_s2st[row];
        r2_lo = st.x; r2_hi = st.y;
        const int4 cc = g_cnt[row * 32 + lane];
        c0 = cc.x; c1 = cc.y; c2 = cc.z; c3 = cc.w;
    }

    float4 f0 = gi[(t0 + 0) * 32], f1 = gi[(t0 + 1) * 32];
    float4 f2 = gi[(t0 + 2) * 32], f3 = gi[(t0 + 3) * 32];
    float4 f4 = gi[(t0 + 4) * 32], f5 = gi[(t0 + 5) * 32];
    float4 f6 = gi[(t0 + 6) * 32], f7 = gi[(t0 + 7) * 32];

    auto stepB = [&](const float4& cur) {
        ull g01 = pk2(cur.x, cur.y), g23 = pk2(cur.z, cur.w);
        walkp(W2h, r2_lo, r2_hi, lane, g01, g23);
        const float2 ga = upk2(g01), gb = upk2(g23);
        const bool p0 = (ga.x >= 1.0f), p1 = (ga.y >= 1.0f);
        const bool p2 = (gb.x >= 1.0f), p3 = (gb.y >= 1.0f);
        const unsigned q0 = __ballot_sync(0xffffffffu, p0);
        const unsigned q1 = __ballot_sync(0xffffffffu, p1);
        const unsigned q2 = __ballot_sync(0xffffffffu, p2);
        const unsigned q3 = __ballot_sync(0xffffffffu, p3);
        r2_lo = (ull)q0 | ((ull)q1 << 32);
        r2_hi = (ull)q2 | ((ull)q3 << 32);
        c0 += p0; c1 += p1; c2 += p2; c3 += p3;
    };

    for (int t = t0; t < t0 + TCH; t += 8) {
        stepB(f0); f0 = gi[(t +  8) * 32];
        stepB(f1); f1 = gi[(t +  9) * 32];
        stepB(f2); f2 = gi[(t + 10) * 32];
        stepB(f3); f3 = gi[(t + 11) * 32];
        stepB(f4); f4 = gi[(t + 12) * 32];
        stepB(f5); f5 = gi[(t + 13) * 32];
        stepB(f6); f6 = gi[(t + 14) * 32];
        stepB(f7); f7 = gi[(t + 15) * 32];
    }

    // save state (cheap; overwritten harmlessly on last chunk)
    if (lane == 0) { ulonglong2 st; st.x = r2_lo; st.y = r2_hi; g_s2st[row] = st; }
    { int4 cc; cc.x = c0; cc.y = c1; cc.z = c2; cc.w = c3; g_cnt[row * 32 + lane] = cc; }

    if (t0 == (NCH - 1) * TCH) {
        const float f0c = (float)c0, f1c = (float)c1, f2c = (float)c2, f3c = (float)c3;
#pragma unroll
        for (int o = 0; o < DOUT; ++o) {
            const float* wr = Wo + o * HD;
            float p = f0c * wr[lane] + f1c * wr[lane + 32]
                    + f2c * wr[lane + 64] + f3c * wr[lane + 96];
#pragma unroll
            for (int s = 16; s; s >>= 1) p += __shfl_xor_sync(0xffffffffu, p, s);
            if (lane == 0) out[row * DOUT + o] = bo[o] + p * (1.0f / (float)TS);
        }
    }
}

extern "C" void kernel_launch(void* const* d_in, const int* in_sizes, int n_in,
                              void* d_out, int out_size)
{
    const float* x   = (const float*)d_in[0];
    const float* Wi1 = (const float*)d_in[1];
    const float* bi1 = (const float*)d_in[2];
    const float* Wh1 = (const float*)d_in[3];
    const float* bh1 = (const float*)d_in[4];
    const float* Wi2 = (const float*)d_in[5];
    const float* bi2 = (const float*)d_in[6];
    const float* Wh2 = (const float*)d_in[7];
    const float* bh2 = (const float*)d_in[8];
    const float* Wo  = (const float*)d_in[9];
    const float* bo  = (const float*)d_in[10];
    float* out = (float*)d_out;

    // one-time host objects (no device memory; work is identical every call)
    static cudaStream_t sA = nullptr, sB = nullptr, sC = nullptr;
    static cudaEvent_t e1[NCH], eA[NCH], eB[NCH], eFin;
    if (sA == nullptr) {
        int lo = 0, hi = 0;
        cudaDeviceGetStreamPriorityRange(&lo, &hi);
        cudaStreamCreateWithPriority(&sA, cudaStreamNonBlocking, hi);
        cudaStreamCreateWithPriority(&sB, cudaStreamNonBlocking, hi);
        cudaStreamCreateWithPriority(&sC, cudaStreamNonBlocking, hi);
        for (int c = 0; c < NCH; ++c) {
            cudaEventCreateWithFlags(&e1[c], cudaEventDisableTiming);
            cudaEventCreateWithFlags(&eA[c], cudaEventDisableTiming);
            cudaEventCreateWithFlags(&eB[c], cudaEventDisableTiming);
        }
        cudaEventCreateWithFlags(&eFin, cudaEventDisableTiming);
    }

    const int k1_smem = (16384 + 128 * XS) * 4;   // 99328 B, 2 CTAs/SM
    const int w_smem  = 16384 * 4;                // 65536 B
    cudaFuncSetAttribute(k1_gemm, cudaFuncAttributeMaxDynamicSharedMemorySize, k1_smem);
    cudaFuncSetAttribute(k2a,  cudaFuncAttributeMaxDynamicSharedMemorySize, w_smem);
    cudaFuncSetAttribute(k2b2, cudaFuncAttributeMaxDynamicSharedMemorySize, w_smem);

    prep<<<64, 256>>>(Wi1, Wh1, Wi2, Wh2);

    for (int c = 0; c < NCH; ++c) {
        const int t0 = c * TCH;
        k1_gemm<<<8 * TCH, 256, k1_smem>>>(x, bi1, bh1, t0);
        cudaEventRecord(e1[c], 0);

        cudaStreamWaitEvent(sA, e1[c], 0);
        k2a<<<NB / 2, 64, w_smem, sA>>>(t0);
        cudaEventRecord(eA[c], sA);

        cudaStreamWaitEvent(sB, eA[c], 0);
        k2b1<<<256, 256, 0, sB>>>(bi2, bh2, t0);
        cudaEventRecord(eB[c], sB);

        cudaStreamWaitEvent(sC, eB[c], 0);
        k2b2<<<NB / 2, 64, w_smem, sC>>>(Wo, bo, out, t0);
    }
    cudaEventRecord(eFin, sC);
    cudaStreamWaitEvent(0, eFin, 0);
}